// round 13
// baseline (speedup 1.0000x reference)
#include <cuda_runtime.h>
#include <cuda_bf16.h>
#include <cuda_fp16.h>
#include <math.h>
#include <stdint.h>

#define NPTS 262144
#define CCH  256
#define KCLS 20
#define BN_TOT 288            // 256 h cols + 32 padded logit cols
#define NB_COLS 144           // N columns per CTA (2 N-tiles)

// ---------------- device globals ----------------
__device__ __half g_fh[(size_t)NPTS * CCH];        // feat in fp16, 128 MB
__device__ __half g_Bh[BN_TOT * CCH];              // B^T fp16 [n][k]
__device__ __half g_hb[(size_t)NPTS * CCH];        // h in fp16, 128 MB
__device__ float g_colsum[CCH];
__device__ float g_colsq[CCH];
__device__ float g_nll;
__device__ float g_vcnt;
__device__ float g_l1;
__device__ float g_cos;
__device__ float g_msum;

// ---------------- PTX helpers (plain-sm_103-safe) ----------------
__device__ __forceinline__ uint32_t smem_u32(const void* p) {
    uint32_t a;
    asm("{ .reg .u64 t; cvta.to.shared.u64 t, %1; cvt.u32.u64 %0, t; }" : "=r"(a) : "l"(p));
    return a;
}
__device__ __forceinline__ void cpa16(uint32_t dst, const void* src) {
    asm volatile("cp.async.cg.shared.global [%0], [%1], 16;" :: "r"(dst), "l"(src));
}
__device__ __forceinline__ void cpa_commit() {
    asm volatile("cp.async.commit_group;" ::: "memory");
}
__device__ __forceinline__ void ldm4(uint32_t* r, uint32_t a) {
    asm volatile("ldmatrix.sync.aligned.m8n8.x4.shared.b16 {%0,%1,%2,%3}, [%4];"
                 : "=r"(r[0]), "=r"(r[1]), "=r"(r[2]), "=r"(r[3]) : "r"(a));
}
__device__ __forceinline__ void ldm2(uint32_t* r, uint32_t a) {
    asm volatile("ldmatrix.sync.aligned.m8n8.x2.shared.b16 {%0,%1}, [%2];"
                 : "=r"(r[0]), "=r"(r[1]) : "r"(a));
}
__device__ __forceinline__ void mma_f16(float& d0, float& d1, float& d2, float& d3,
                                        uint32_t a0, uint32_t a1, uint32_t a2, uint32_t a3,
                                        uint32_t b0, uint32_t b1) {
    asm volatile("mma.sync.aligned.m16n8k16.row.col.f32.f16.f16.f32 "
                 "{%0,%1,%2,%3}, {%4,%5,%6,%7}, {%8,%9}, {%0,%1,%2,%3};"
                 : "+f"(d0), "+f"(d1), "+f"(d2), "+f"(d3)
                 : "r"(a0), "r"(a1), "r"(a2), "r"(a3), "r"(b0), "r"(b1));
}
__device__ __forceinline__ uint32_t pkh(__half a, __half b) {
    __half2 t = __halves2half2(a, b);
    return *(uint32_t*)&t;
}

// SMEM stage layout (bytes). Row stride 144 B (36 words ≡ 4 mod 32 -> conflict-free ldmatrix).
#define RSTRIDE 144
#define A_OFF 0                       // 128 rows * 144 = 18432
#define B_OFF 18432                   // 144 rows * 144 = 20736
#define STAGE 39168
#define NSTAGE 2
#define DYN_SMEM (NSTAGE * STAGE)

// ---------------- kernel 1: build B^T fp16 + zero accumulators ----------------
__global__ void convw_kernel(const float* __restrict__ w1, const float* __restrict__ ws) {
    int n = blockIdx.x;    // 0..287 output channel
    int k = threadIdx.x;   // 0..255 input channel
    if (n == 0) {
        g_colsum[k] = 0.f;
        g_colsq[k]  = 0.f;
        if (k == 0) {
            g_nll = 0.f; g_vcnt = 0.f; g_l1 = 0.f; g_cos = 0.f; g_msum = 0.f;
        }
    }
    float v;
    if (n < 256)             v = w1[(size_t)k * 256 + n];
    else if (n - 256 < KCLS) v = ws[k * KCLS + (n - 256)];
    else                     v = 0.f;
    g_Bh[n * 256 + k] = __float2half_rn(v);
}

// ---------------- kernel 2: convert feat fp32 -> fp16 (streaming) ----------------
__global__ __launch_bounds__(256)
void convfeat_kernel(const float* __restrict__ feat) {
    size_t i = (size_t)blockIdx.x * 256 + threadIdx.x;
    const float4* f4 = (const float4*)feat;
    uint2* h2 = (uint2*)g_fh;
    const size_t stride = (size_t)16384 * 256;
#pragma unroll
    for (int t = 0; t < 4; t++, i += stride) {
        float4 v = f4[i];
        uint2 o;
        o.x = pkh(__float2half_rn(v.x), __float2half_rn(v.y));
        o.y = pkh(__float2half_rn(v.z), __float2half_rn(v.w));
        h2[i] = o;
    }
}

// ---------------- GEMM load (K=64 chunk, all cp.async) ----------------
__device__ __forceinline__ void ab_issue(int rowBase, int nbase, int k0,
                                         uint32_t S, int tid) {
#pragma unroll
    for (int t = 0; t < 4; t++) {
        int i = tid + t * 256;
        int r = i >> 3, s = i & 7;
        cpa16(S + A_OFF + (uint32_t)r * RSTRIDE + (uint32_t)s * 16,
              g_fh + (size_t)(rowBase + r) * 256 + k0 + s * 8);
    }
#pragma unroll
    for (int t = 0; t < 5; t++) {
        int i = tid + t * 256;
        if (i < 1152) {
            int n = i >> 3, s = i & 7;
            cpa16(S + B_OFF + (uint32_t)n * RSTRIDE + (uint32_t)s * 16,
                  g_Bh + (size_t)(nbase + n) * 256 + k0 + s * 8);
        }
    }
}

// ---------------- kernel 3: fused GEMM (fp16 HMMA) + epilogue ----------------
__global__ __launch_bounds__(256, 2)
void gemm_kernel(const float* __restrict__ b1v,
                 const float* __restrict__ bsv,
                 const int* __restrict__ segment) {
    extern __shared__ char dsm[];
    __shared__ float s_b1[256];
    __shared__ float s_bs[32];
    __shared__ float s_lg[128][33];
    __shared__ float s_scs[256];
    __shared__ float s_scq[256];
    __shared__ float s_nv[2];

    const int tid = threadIdx.x;
    const int wid = tid >> 5, lane = tid & 31;
    const int nb = blockIdx.x;                 // 0..1 N tile
    const int rowBase = blockIdx.y * 128;
    const int nbase = nb * NB_COLS;
    const int wm = wid & 3, wn = wid >> 2;     // 4m x 2n warps
    const int mwb = wm * 32;
    const int g = lane >> 2, tg = lane & 3;

    const uint32_t sb = smem_u32(dsm);

    if (tid < 256) { s_b1[tid] = b1v[tid]; s_scs[tid] = 0.f; s_scq[tid] = 0.f; }
    if (tid < 32)  s_bs[tid] = (tid < KCLS) ? bsv[tid] : 0.f;
    if (tid == 0)  { s_nv[0] = 0.f; s_nv[1] = 0.f; }

    float acc[2][9][4];
#pragma unroll
    for (int f = 0; f < 2; f++)
#pragma unroll
        for (int j = 0; j < 9; j++)
#pragma unroll
            for (int q = 0; q < 4; q++) acc[f][j][q] = 0.f;

    const uint32_t aOff = A_OFF + (uint32_t)(mwb + (lane & 15)) * RSTRIDE
                        + (uint32_t)(lane >> 4) * 16;
    const uint32_t bOff4 = B_OFF
        + (uint32_t)(wn * 72 + (lane & 7) + 8 * ((lane >> 4) & 1)) * RSTRIDE
        + (uint32_t)((lane >> 3) & 1) * 16;
    const uint32_t bOff2 = B_OFF
        + (uint32_t)(wn * 72 + 64 + (lane & 7)) * RSTRIDE
        + (uint32_t)((lane >> 3) & 1) * 16;

    ab_issue(rowBase, nbase, 0, sb, tid);          cpa_commit();
    ab_issue(rowBase, nbase, 64, sb + STAGE, tid); cpa_commit();

#pragma unroll 1
    for (int c = 0; c < 4; c++) {
        if (c < 3) asm volatile("cp.async.wait_group 1;" ::: "memory");
        else       asm volatile("cp.async.wait_group 0;" ::: "memory");
        __syncthreads();

        const uint32_t S = sb + (uint32_t)((c & 1) * STAGE);
#pragma unroll
        for (int ks = 0; ks < 4; ks++) {
            const uint32_t ko = (uint32_t)ks * 32;
            uint32_t a0[4], a1[4];
            ldm4(a0, S + aOff + ko);
            ldm4(a1, S + aOff + 16 * RSTRIDE + ko);
#pragma unroll
            for (int jj = 0; jj < 4; jj++) {
                uint32_t b4[4];
                ldm4(b4, S + bOff4 + (uint32_t)jj * (16 * RSTRIDE) + ko);
                mma_f16(acc[0][2 * jj][0], acc[0][2 * jj][1], acc[0][2 * jj][2], acc[0][2 * jj][3],
                        a0[0], a0[1], a0[2], a0[3], b4[0], b4[1]);
                mma_f16(acc[1][2 * jj][0], acc[1][2 * jj][1], acc[1][2 * jj][2], acc[1][2 * jj][3],
                        a1[0], a1[1], a1[2], a1[3], b4[0], b4[1]);
                mma_f16(acc[0][2 * jj + 1][0], acc[0][2 * jj + 1][1], acc[0][2 * jj + 1][2], acc[0][2 * jj + 1][3],
                        a0[0], a0[1], a0[2], a0[3], b4[2], b4[3]);
                mma_f16(acc[1][2 * jj + 1][0], acc[1][2 * jj + 1][1], acc[1][2 * jj + 1][2], acc[1][2 * jj + 1][3],
                        a1[0], a1[1], a1[2], a1[3], b4[2], b4[3]);
            }
            uint32_t b2r[2];
            ldm2(b2r, S + bOff2 + ko);
            mma_f16(acc[0][8][0], acc[0][8][1], acc[0][8][2], acc[0][8][3],
                    a0[0], a0[1], a0[2], a0[3], b2r[0], b2r[1]);
            mma_f16(acc[1][8][0], acc[1][8][1], acc[1][8][2], acc[1][8][3],
                    a1[0], a1[1], a1[2], a1[3], b2r[0], b2r[1]);
        }

        if (c < 2) {
            __syncthreads();
            ab_issue(rowBase, nbase, (c + 2) * 64, S, tid);
            cpa_commit();
        }
    }

    // ---------------- epilogue ----------------
    uint32_t* hb32 = (uint32_t*)g_hb;
#pragma unroll
    for (int j = 0; j < 9; j++) {
        int gc = nbase + wn * 72 + j * 8 + tg * 2;
        if (gc < 256) {
            float bb0 = s_b1[gc], bb1 = s_b1[gc + 1];
            float cs0 = 0.f, cq0 = 0.f, cs1 = 0.f, cq1 = 0.f;
#pragma unroll
            for (int f = 0; f < 2; f++) {
                int r = rowBase + mwb + f * 16 + g;
                float v00 = acc[f][j][0] + bb0;
                float v01 = acc[f][j][1] + bb1;
                float v10 = acc[f][j][2] + bb0;
                float v11 = acc[f][j][3] + bb1;
                hb32[((size_t)r * 256 + gc) >> 1] =
                    pkh(__float2half_rn(v00), __float2half_rn(v01));
                hb32[((size_t)(r + 8) * 256 + gc) >> 1] =
                    pkh(__float2half_rn(v10), __float2half_rn(v11));
                cs0 += v00 + v10;  cq0 += v00 * v00 + v10 * v10;
                cs1 += v01 + v11;  cq1 += v01 * v01 + v11 * v11;
            }
#pragma unroll
            for (int o = 4; o <= 16; o <<= 1) {
                cs0 += __shfl_xor_sync(0xffffffffu, cs0, o);
                cq0 += __shfl_xor_sync(0xffffffffu, cq0, o);
                cs1 += __shfl_xor_sync(0xffffffffu, cs1, o);
                cq1 += __shfl_xor_sync(0xffffffffu, cq1, o);
            }
            if (g == 0) {
                atomicAdd(&s_scs[gc], cs0);     atomicAdd(&s_scq[gc], cq0);
                atomicAdd(&s_scs[gc + 1], cs1); atomicAdd(&s_scq[gc + 1], cq1);
            }
        } else {
            int lc = gc - 256;
            float bb0 = s_bs[lc], bb1 = s_bs[lc + 1];
#pragma unroll
            for (int f = 0; f < 2; f++) {
                int r = mwb + f * 16 + g;
                s_lg[r][lc]         = acc[f][j][0] + bb0;
                s_lg[r][lc + 1]     = acc[f][j][1] + bb1;
                s_lg[r + 8][lc]     = acc[f][j][2] + bb0;
                s_lg[r + 8][lc + 1] = acc[f][j][3] + bb1;
            }
        }
    }
    __syncthreads();

    if (nb == 1 && tid < 128) {
        int row = tid;
        float m = -1e30f;
        float lg[KCLS];
#pragma unroll
        for (int q = 0; q < KCLS; q++) { lg[q] = s_lg[row][q]; m = fmaxf(m, lg[q]); }
        float se = 0.f;
#pragma unroll
        for (int q = 0; q < KCLS; q++) se += expf(lg[q] - m);
        int t = segment[rowBase + row];
        bool valid = (t != -1);
        float picked = s_lg[row][valid ? t : 0];
        float vf = valid ? 1.f : 0.f;
        float nll = (m + logf(se) - picked) * vf;
#pragma unroll
        for (int o = 16; o > 0; o >>= 1) {
            nll += __shfl_xor_sync(0xffffffffu, nll, o);
            vf  += __shfl_xor_sync(0xffffffffu, vf, o);
        }
        if (lane == 0) { atomicAdd(&s_nv[0], nll); atomicAdd(&s_nv[1], vf); }
    }
    {
        int lo = nb * NB_COLS;
        int hi = nb ? 256 : NB_COLS;
        for (int i = lo + tid; i < hi; i += 256) {
            atomicAdd(&g_colsum[i], s_scs[i]);
            atomicAdd(&g_colsq[i], s_scq[i]);
        }
    }
    __syncthreads();
    if (nb == 1 && tid == 0) { atomicAdd(&g_nll, s_nv[0]); atomicAdd(&g_vcnt, s_nv[1]); }
}

// ---------------- kernel 4: BN(inlined)+ReLU+bias head+losses, 4pts/warp parallel ----------------
__global__ __launch_bounds__(256)
void bias_kernel(const float* __restrict__ coord,
                 const float* __restrict__ centroid,
                 const int* __restrict__ instance,
                 const float* __restrict__ gamma,
                 const float* __restrict__ beta,
                 const float* __restrict__ w2,
                 const float* __restrict__ b2) {
    __shared__ float s_a[CCH], s_sc[CCH];
    __shared__ float s_w2t[3][CCH];
    __shared__ float red[8][3];

    const int tid = threadIdx.x;
    // inlined bnprep: every CTA computes BN affine params
    {
        const float invN = 1.0f / (float)NPTS;
        float mu  = g_colsum[tid] * invN;
        float var = g_colsq[tid] * invN - mu * mu;
        float a = gamma[tid] / sqrtf(var + 1e-3f);
        s_a[tid]  = a;
        s_sc[tid] = beta[tid] - mu * a;           // v = h*a + sc
        s_w2t[0][tid] = w2[tid * 3 + 0];
        s_w2t[1][tid] = w2[tid * 3 + 1];
        s_w2t[2][tid] = w2[tid * 3 + 2];
    }
    __syncthreads();

    const int warp = tid >> 5, lane = tid & 31;
    const int grp = lane >> 3, l = lane & 7;      // 4 groups of 8 lanes
    const float b2x = b2[0], b2y = b2[1], b2z = b2[2];

    float l1acc = 0.f, cosacc = 0.f, mcount = 0.f;

#pragma unroll 1
    for (int it = 0; it < 4; it++) {
        int n = blockIdx.x * 128 + warp * 16 + it * 4 + grp;
        const uint4* hp = (const uint4*)(g_hb) + (size_t)n * 32;
        float d0 = 0.f, d1 = 0.f, d2 = 0.f;
#pragma unroll
        for (int u = 0; u < 4; u++) {
            int q = l + 8 * u;                    // uint4 index; channels 8q..8q+7
            uint4 hv = hp[q];
            int c0 = q * 8;
            float4 a0 = *(const float4*)&s_a[c0];
            float4 a1 = *(const float4*)&s_a[c0 + 4];
            float4 sc0 = *(const float4*)&s_sc[c0];
            float4 sc1 = *(const float4*)&s_sc[c0 + 4];
            __half2 h01 = *(__half2*)&hv.x;
            __half2 h23 = *(__half2*)&hv.y;
            __half2 h45 = *(__half2*)&hv.z;
            __half2 h67 = *(__half2*)&hv.w;
            float v0 = fmaxf(__half2float(h01.x) * a0.x + sc0.x, 0.f);
            float v1 = fmaxf(__half2float(h01.y) * a0.y + sc0.y, 0.f);
            float v2 = fmaxf(__half2float(h23.x) * a0.z + sc0.z, 0.f);
            float v3 = fmaxf(__half2float(h23.y) * a0.w + sc0.w, 0.f);
            float v4 = fmaxf(__half2float(h45.x) * a1.x + sc1.x, 0.f);
            float v5 = fmaxf(__half2float(h45.y) * a1.y + sc1.y, 0.f);
            float v6 = fmaxf(__half2float(h67.x) * a1.z + sc1.z, 0.f);
            float v7 = fmaxf(__half2float(h67.y) * a1.w + sc1.w, 0.f);
#pragma unroll
            for (int p = 0; p < 3; p++) {
                float4 w0 = *(const float4*)&s_w2t[p][c0];
                float4 w1v = *(const float4*)&s_w2t[p][c0 + 4];
                float dd = v0 * w0.x + v1 * w0.y + v2 * w0.z + v3 * w0.w
                         + v4 * w1v.x + v5 * w1v.y + v6 * w1v.z + v7 * w1v.w;
                if (p == 0) d0 += dd; else if (p == 1) d1 += dd; else d2 += dd;
            }
        }
        // reduce across 8 lanes of each group (4 points in parallel)
#pragma unroll
        for (int o = 1; o <= 4; o <<= 1) {
            d0 += __shfl_xor_sync(0xffffffffu, d0, o);
            d1 += __shfl_xor_sync(0xffffffffu, d1, o);
            d2 += __shfl_xor_sync(0xffffffffu, d2, o);
        }
        if (l == 0) {
            float px = d0 + b2x, py = d1 + b2y, pz = d2 + b2z;
            float gx = centroid[3 * n + 0] - coord[3 * n + 0];
            float gy = centroid[3 * n + 1] - coord[3 * n + 1];
            float gz = centroid[3 * n + 2] - coord[3 * n + 2];
            float mask = (instance[n] != -1) ? 1.f : 0.f;
            float l1 = fabsf(px - gx) + fabsf(py - gy) + fabsf(pz - gz);
            float pn = sqrtf(px * px + py * py + pz * pz) + 1e-8f;
            float gn = sqrtf(gx * gx + gy * gy + gz * gz) + 1e-8f;
            float cs = -(px * gx + py * gy + pz * gz) / (pn * gn);
            l1acc  += l1 * mask;
            cosacc += cs * mask;
            mcount += mask;
        }
    }
    // combine the 4 group-leaders (lanes 0,8,16,24)
#pragma unroll
    for (int o = 8; o <= 16; o <<= 1) {
        l1acc  += __shfl_xor_sync(0xffffffffu, l1acc, o);
        cosacc += __shfl_xor_sync(0xffffffffu, cosacc, o);
        mcount += __shfl_xor_sync(0xffffffffu, mcount, o);
    }
    if (lane == 0) {
        red[warp][0] = l1acc;
        red[warp][1] = cosacc;
        red[warp][2] = mcount;
    }
    __syncthreads();
    if (tid == 0) {
        float s0 = 0.f, s1 = 0.f, s2 = 0.f;
        for (int w = 0; w < 8; w++) { s0 += red[w][0]; s1 += red[w][1]; s2 += red[w][2]; }
        atomicAdd(&g_l1, s0);
        atomicAdd(&g_cos, s1);
        atomicAdd(&g_msum, s2);
    }
}

// ---------------- kernel 5: finalize ----------------
__global__ void final_kernel(float* __restrict__ out) {
    float seg_loss = g_nll / (g_vcnt + 1e-8f);
    float l1_loss  = g_l1  / (g_msum + 1e-8f);
    float cos_loss = g_cos / (g_msum + 1e-8f);
    out[0] = seg_loss + l1_loss + cos_loss;
    out[1] = seg_loss;
    out[2] = l1_loss;
    out[3] = cos_loss;
}

// ---------------- launcher ----------------
extern "C" void kernel_launch(void* const* d_in, const int* in_sizes, int n_in,
                              void* d_out, int out_size) {
    const float* feat     = (const float*)d_in[0];
    const float* coord    = (const float*)d_in[1];
    const float* centroid = (const float*)d_in[2];
    const int*   segment  = (const int*)d_in[3];
    const int*   instance = (const int*)d_in[4];
    const float* w1       = (const float*)d_in[5];
    const float* b1       = (const float*)d_in[6];
    const float* gamma    = (const float*)d_in[7];
    const float* beta     = (const float*)d_in[8];
    const float* w2       = (const float*)d_in[9];
    const float* b2       = (const float*)d_in[10];
    const float* ws       = (const float*)d_in[11];
    const float* bs       = (const float*)d_in[12];
    float* out = (float*)d_out;

    static int smem_set = 0;
    if (!smem_set) {
        cudaFuncSetAttribute(gemm_kernel, cudaFuncAttributeMaxDynamicSharedMemorySize, DYN_SMEM);
        smem_set = 1;
    }

    // bias_kernel is launch #4 -> profiled by ncu.
    convw_kernel<<<BN_TOT, 256>>>(w1, ws);
    convfeat_kernel<<<16384, 256>>>(feat);
    gemm_kernel<<<dim3(2, NPTS / 128), 256, DYN_SMEM>>>(b1, bs, segment);
    bias_kernel<<<NPTS / 128, 256>>>(coord, centroid, instance, gamma, beta, w2, b2);
    final_kernel<<<1, 1>>>(out);
}

// round 14
// speedup vs baseline: 1.1862x; 1.1862x over previous
#include <cuda_runtime.h>
#include <cuda_bf16.h>
#include <cuda_fp16.h>
#include <math.h>
#include <stdint.h>

#define NPTS 262144
#define CCH  256
#define KCLS 20
#define BN_TOT 288            // 256 h cols + 32 padded logit cols
#define NB_COLS 144           // N columns per CTA (2 N-tiles)

// ---------------- device globals ----------------
__device__ __half g_Bh[BN_TOT * CCH];              // B^T fp16 [n][k]
__device__ __half g_hb[(size_t)NPTS * CCH];        // h in fp16, 128 MB
__device__ float g_colsum[CCH];
__device__ float g_colsq[CCH];
__device__ float g_nll;
__device__ float g_vcnt;
__device__ float g_l1;
__device__ float g_cos;
__device__ float g_msum;

// ---------------- PTX helpers (plain-sm_103-safe) ----------------
__device__ __forceinline__ uint32_t smem_u32(const void* p) {
    uint32_t a;
    asm("{ .reg .u64 t; cvta.to.shared.u64 t, %1; cvt.u32.u64 %0, t; }" : "=r"(a) : "l"(p));
    return a;
}
__device__ __forceinline__ void sts64(uint32_t a, uint32_t x, uint32_t y) {
    asm volatile("st.shared.v2.b32 [%0], {%1,%2};" :: "r"(a), "r"(x), "r"(y));
}
__device__ __forceinline__ void cpa16(uint32_t dst, const void* src) {
    asm volatile("cp.async.cg.shared.global [%0], [%1], 16;" :: "r"(dst), "l"(src));
}
__device__ __forceinline__ void cpa_commit() {
    asm volatile("cp.async.commit_group;" ::: "memory");
}
__device__ __forceinline__ void ldm4(uint32_t* r, uint32_t a) {
    asm volatile("ldmatrix.sync.aligned.m8n8.x4.shared.b16 {%0,%1,%2,%3}, [%4];"
                 : "=r"(r[0]), "=r"(r[1]), "=r"(r[2]), "=r"(r[3]) : "r"(a));
}
__device__ __forceinline__ void ldm2(uint32_t* r, uint32_t a) {
    asm volatile("ldmatrix.sync.aligned.m8n8.x2.shared.b16 {%0,%1}, [%2];"
                 : "=r"(r[0]), "=r"(r[1]) : "r"(a));
}
__device__ __forceinline__ void mma_f16(float& d0, float& d1, float& d2, float& d3,
                                        uint32_t a0, uint32_t a1, uint32_t a2, uint32_t a3,
                                        uint32_t b0, uint32_t b1) {
    asm volatile("mma.sync.aligned.m16n8k16.row.col.f32.f16.f16.f32 "
                 "{%0,%1,%2,%3}, {%4,%5,%6,%7}, {%8,%9}, {%0,%1,%2,%3};"
                 : "+f"(d0), "+f"(d1), "+f"(d2), "+f"(d3)
                 : "r"(a0), "r"(a1), "r"(a2), "r"(a3), "r"(b0), "r"(b1));
}
__device__ __forceinline__ uint32_t pkh(__half a, __half b) {
    __half2 t = __halves2half2(a, b);
    return *(uint32_t*)&t;
}

// SMEM stage layout (bytes). Row stride 144 B (36 words ≡ 4 mod 32 -> conflict-free ldmatrix).
#define RSTRIDE 144
#define A_OFF 0                       // 128 rows * 144 = 18432
#define B_OFF 18432                   // 144 rows * 144 = 20736
#define STAGE 39168
#define NSTAGE 2
#define DYN_SMEM (NSTAGE * STAGE)

// ---------------- kernel 1: build B^T fp16 + zero accumulators ----------------
__global__ void convw_kernel(const float* __restrict__ w1, const float* __restrict__ ws) {
    int n = blockIdx.x;    // 0..287 output channel
    int k = threadIdx.x;   // 0..255 input channel
    if (n == 0) {
        g_colsum[k] = 0.f;
        g_colsq[k]  = 0.f;
        if (k == 0) {
            g_nll = 0.f; g_vcnt = 0.f; g_l1 = 0.f; g_cos = 0.f; g_msum = 0.f;
        }
    }
    float v;
    if (n < 256)             v = w1[(size_t)k * 256 + n];
    else if (n - 256 < KCLS) v = ws[k * KCLS + (n - 256)];
    else                     v = 0.f;
    g_Bh[n * 256 + k] = __float2half_rn(v);
}

// ---------------- GEMM load helpers (K=64 chunks, R10-proven) ----------------
__device__ __forceinline__ void a_issue(const float* __restrict__ feat,
                                        int rowBase, int k0, int tid, float4* va) {
#pragma unroll
    for (int t = 0; t < 8; t++) {
        int i = tid + t * 256;
        int r = i >> 4, s = i & 15;
        va[t] = *(const float4*)(feat + (size_t)(rowBase + r) * 256 + k0 + s * 4);
    }
}
__device__ __forceinline__ void a_store(uint32_t S, int tid, const float4* va) {
#pragma unroll
    for (int t = 0; t < 8; t++) {
        int i = tid + t * 256;
        int r = i >> 4, s = i & 15;
        uint32_t p0 = pkh(__float2half_rn(va[t].x), __float2half_rn(va[t].y));
        uint32_t p1 = pkh(__float2half_rn(va[t].z), __float2half_rn(va[t].w));
        sts64(S + A_OFF + (uint32_t)r * RSTRIDE + (uint32_t)s * 8, p0, p1);
    }
}
__device__ __forceinline__ void b_issue(int nbase, int k0, uint32_t S, int tid) {
#pragma unroll
    for (int t = 0; t < 5; t++) {
        int i = tid + t * 256;
        if (i < 1152) {
            int n = i >> 3, s = i & 7;
            cpa16(S + B_OFF + (uint32_t)n * RSTRIDE + (uint32_t)s * 16,
                  g_Bh + (size_t)(nbase + n) * 256 + k0 + s * 8);
        }
    }
}

// ---------------- kernel 2: fused GEMM (fp16 HMMA, K=64, 2-stage, 2 CTA/SM) ----------------
__global__ __launch_bounds__(256, 2)
void gemm_kernel(const float* __restrict__ feat,
                 const float* __restrict__ b1v,
                 const float* __restrict__ bsv,
                 const int* __restrict__ segment) {
    extern __shared__ char dsm[];
    __shared__ float s_b1[256];
    __shared__ float s_bs[32];
    __shared__ float s_lg[128][33];
    __shared__ float s_scs[256];
    __shared__ float s_scq[256];
    __shared__ float s_nv[2];

    const int tid = threadIdx.x;
    const int wid = tid >> 5, lane = tid & 31;
    const int nb = blockIdx.x;                 // 0..1 N tile
    const int rowBase = blockIdx.y * 128;
    const int nbase = nb * NB_COLS;
    const int wm = wid & 3, wn = wid >> 2;     // 4m x 2n warps
    const int mwb = wm * 32;
    const int g = lane >> 2, tg = lane & 3;

    const uint32_t sb = smem_u32(dsm);

    if (tid < 256) { s_b1[tid] = b1v[tid]; s_scs[tid] = 0.f; s_scq[tid] = 0.f; }
    if (tid < 32)  s_bs[tid] = (tid < KCLS) ? bsv[tid] : 0.f;
    if (tid == 0)  { s_nv[0] = 0.f; s_nv[1] = 0.f; }

    float acc[2][9][4];
#pragma unroll
    for (int f = 0; f < 2; f++)
#pragma unroll
        for (int j = 0; j < 9; j++)
#pragma unroll
            for (int q = 0; q < 4; q++) acc[f][j][q] = 0.f;

    const uint32_t aOff = A_OFF + (uint32_t)(mwb + (lane & 15)) * RSTRIDE
                        + (uint32_t)(lane >> 4) * 16;
    const uint32_t bOff4 = B_OFF
        + (uint32_t)(wn * 72 + (lane & 7) + 8 * ((lane >> 4) & 1)) * RSTRIDE
        + (uint32_t)((lane >> 3) & 1) * 16;
    const uint32_t bOff2 = B_OFF
        + (uint32_t)(wn * 72 + 64 + (lane & 7)) * RSTRIDE
        + (uint32_t)((lane >> 3) & 1) * 16;

    // ---- pipeline prologue ----
    float4 regA[8];
    a_issue(feat, rowBase, 0, tid, regA);
    b_issue(nbase, 0, sb, tid);
    cpa_commit();
    a_store(sb, tid, regA);                  // A(0)
    a_issue(feat, rowBase, 64, tid, regA);   // prefetch A(1)
    asm volatile("cp.async.wait_group 0;" ::: "memory");
    __syncthreads();                         // stage0 fully ready
    b_issue(nbase, 64, sb + STAGE, tid);     // B(1)
    cpa_commit();

#pragma unroll 1
    for (int c = 0; c < 4; c++) {
        const uint32_t S = sb + (uint32_t)((c & 1) * STAGE);
#pragma unroll
        for (int ks = 0; ks < 4; ks++) {
            const uint32_t ko = (uint32_t)ks * 32;
            uint32_t a0[4], a1[4];
            ldm4(a0, S + aOff + ko);
            ldm4(a1, S + aOff + 16 * RSTRIDE + ko);
#pragma unroll
            for (int jj = 0; jj < 4; jj++) {
                uint32_t b4[4];
                ldm4(b4, S + bOff4 + (uint32_t)jj * (16 * RSTRIDE) + ko);
                mma_f16(acc[0][2 * jj][0], acc[0][2 * jj][1], acc[0][2 * jj][2], acc[0][2 * jj][3],
                        a0[0], a0[1], a0[2], a0[3], b4[0], b4[1]);
                mma_f16(acc[1][2 * jj][0], acc[1][2 * jj][1], acc[1][2 * jj][2], acc[1][2 * jj][3],
                        a1[0], a1[1], a1[2], a1[3], b4[0], b4[1]);
                mma_f16(acc[0][2 * jj + 1][0], acc[0][2 * jj + 1][1], acc[0][2 * jj + 1][2], acc[0][2 * jj + 1][3],
                        a0[0], a0[1], a0[2], a0[3], b4[2], b4[3]);
                mma_f16(acc[1][2 * jj + 1][0], acc[1][2 * jj + 1][1], acc[1][2 * jj + 1][2], acc[1][2 * jj + 1][3],
                        a1[0], a1[1], a1[2], a1[3], b4[2], b4[3]);
            }
            uint32_t b2r[2];
            ldm2(b2r, S + bOff2 + ko);
            mma_f16(acc[0][8][0], acc[0][8][1], acc[0][8][2], acc[0][8][3],
                    a0[0], a0[1], a0[2], a0[3], b2r[0], b2r[1]);
            mma_f16(acc[1][8][0], acc[1][8][1], acc[1][8][2], acc[1][8][3],
                    a1[0], a1[1], a1[2], a1[3], b2r[0], b2r[1]);
        }

        if (c < 3) {
            const uint32_t Sn = sb + (uint32_t)(((c + 1) & 1) * STAGE);
            a_store(Sn, tid, regA);                               // A(c+1)
            if (c < 2) a_issue(feat, rowBase, (c + 2) * 64, tid, regA);
            asm volatile("cp.async.wait_group 0;" ::: "memory");  // B(c+1)
            __syncthreads();
            if (c < 2) {
                b_issue(nbase, (c + 2) * 64, S, tid);
                cpa_commit();
            }
        }
    }

    // ---------------- epilogue ----------------
    uint32_t* hb32 = (uint32_t*)g_hb;
#pragma unroll
    for (int j = 0; j < 9; j++) {
        int gc = nbase + wn * 72 + j * 8 + tg * 2;
        if (gc < 256) {
            float bb0 = s_b1[gc], bb1 = s_b1[gc + 1];
            float cs0 = 0.f, cq0 = 0.f, cs1 = 0.f, cq1 = 0.f;
#pragma unroll
            for (int f = 0; f < 2; f++) {
                int r = rowBase + mwb + f * 16 + g;
                float v00 = acc[f][j][0] + bb0;
                float v01 = acc[f][j][1] + bb1;
                float v10 = acc[f][j][2] + bb0;
                float v11 = acc[f][j][3] + bb1;
                hb32[((size_t)r * 256 + gc) >> 1] =
                    pkh(__float2half_rn(v00), __float2half_rn(v01));
                hb32[((size_t)(r + 8) * 256 + gc) >> 1] =
                    pkh(__float2half_rn(v10), __float2half_rn(v11));
                cs0 += v00 + v10;  cq0 += v00 * v00 + v10 * v10;
                cs1 += v01 + v11;  cq1 += v01 * v01 + v11 * v11;
            }
#pragma unroll
            for (int o = 4; o <= 16; o <<= 1) {
                cs0 += __shfl_xor_sync(0xffffffffu, cs0, o);
                cq0 += __shfl_xor_sync(0xffffffffu, cq0, o);
                cs1 += __shfl_xor_sync(0xffffffffu, cs1, o);
                cq1 += __shfl_xor_sync(0xffffffffu, cq1, o);
            }
            if (g == 0) {
                atomicAdd(&s_scs[gc], cs0);     atomicAdd(&s_scq[gc], cq0);
                atomicAdd(&s_scs[gc + 1], cs1); atomicAdd(&s_scq[gc + 1], cq1);
            }
        } else {
            int lc = gc - 256;
            float bb0 = s_bs[lc], bb1 = s_bs[lc + 1];
#pragma unroll
            for (int f = 0; f < 2; f++) {
                int r = mwb + f * 16 + g;
                s_lg[r][lc]         = acc[f][j][0] + bb0;
                s_lg[r][lc + 1]     = acc[f][j][1] + bb1;
                s_lg[r + 8][lc]     = acc[f][j][2] + bb0;
                s_lg[r + 8][lc + 1] = acc[f][j][3] + bb1;
            }
        }
    }
    __syncthreads();

    if (nb == 1 && tid < 128) {
        int row = tid;
        float m = -1e30f;
        float lg[KCLS];
#pragma unroll
        for (int q = 0; q < KCLS; q++) { lg[q] = s_lg[row][q]; m = fmaxf(m, lg[q]); }
        float se = 0.f;
#pragma unroll
        for (int q = 0; q < KCLS; q++) se += expf(lg[q] - m);
        int t = segment[rowBase + row];
        bool valid = (t != -1);
        float picked = s_lg[row][valid ? t : 0];
        float vf = valid ? 1.f : 0.f;
        float nll = (m + logf(se) - picked) * vf;
#pragma unroll
        for (int o = 16; o > 0; o >>= 1) {
            nll += __shfl_xor_sync(0xffffffffu, nll, o);
            vf  += __shfl_xor_sync(0xffffffffu, vf, o);
        }
        if (lane == 0) { atomicAdd(&s_nv[0], nll); atomicAdd(&s_nv[1], vf); }
    }
    {
        int lo = nb * NB_COLS;
        int hi = nb ? 256 : NB_COLS;
        for (int i = lo + tid; i < hi; i += 256) {
            atomicAdd(&g_colsum[i], s_scs[i]);
            atomicAdd(&g_colsq[i], s_scq[i]);
        }
    }
    __syncthreads();
    if (nb == 1 && tid == 0) { atomicAdd(&g_nll, s_nv[0]); atomicAdd(&g_vcnt, s_nv[1]); }
}

// ---------------- kernel 3: bias v3 — params in regs, 4-pt parallel reductions ----------------
__global__ __launch_bounds__(256, 3)
void bias_kernel(const float* __restrict__ coord,
                 const float* __restrict__ centroid,
                 const int* __restrict__ instance,
                 const float* __restrict__ gamma,
                 const float* __restrict__ beta,
                 const float* __restrict__ w2,
                 const float* __restrict__ b2) {
    __shared__ float red[8][3];

    const int tid = threadIdx.x;
    const int warp = tid >> 5, lane = tid & 31;
    const int c0 = lane * 8;

    // per-lane BN-affine + w2 params for its 8 channels (registers)
    float pa[8], psc[8], pw0[8], pw1[8], pw2[8];
    const float invN = 1.0f / (float)NPTS;
#pragma unroll
    for (int i = 0; i < 8; i++) {
        int c = c0 + i;
        float mu  = g_colsum[c] * invN;
        float var = g_colsq[c] * invN - mu * mu;
        float a = gamma[c] * rsqrtf(var + 1e-3f);
        pa[i]  = a;
        psc[i] = beta[c] - mu * a;
        pw0[i] = w2[c * 3 + 0];
        pw1[i] = w2[c * 3 + 1];
        pw2[i] = w2[c * 3 + 2];
    }
    const float b2x = b2[0], b2y = b2[1], b2z = b2[2];

    float l1acc = 0.f, cosacc = 0.f, mcount = 0.f;
    const int base = (blockIdx.x * 8 + warp) * 32;

#pragma unroll 2
    for (int it = 0; it < 8; it++) {
        int n0 = base + it * 4;
        float d[4][3];
#pragma unroll
        for (int p = 0; p < 4; p++) {
            uint4 hv = *(const uint4*)(g_hb + (size_t)(n0 + p) * 256 + c0);
            __half2 h01 = *(__half2*)&hv.x;
            __half2 h23 = *(__half2*)&hv.y;
            __half2 h45 = *(__half2*)&hv.z;
            __half2 h67 = *(__half2*)&hv.w;
            float v0 = fmaxf(__half2float(h01.x) * pa[0] + psc[0], 0.f);
            float v1 = fmaxf(__half2float(h01.y) * pa[1] + psc[1], 0.f);
            float v2 = fmaxf(__half2float(h23.x) * pa[2] + psc[2], 0.f);
            float v3 = fmaxf(__half2float(h23.y) * pa[3] + psc[3], 0.f);
            float v4 = fmaxf(__half2float(h45.x) * pa[4] + psc[4], 0.f);
            float v5 = fmaxf(__half2float(h45.y) * pa[5] + psc[5], 0.f);
            float v6 = fmaxf(__half2float(h67.x) * pa[6] + psc[6], 0.f);
            float v7 = fmaxf(__half2float(h67.y) * pa[7] + psc[7], 0.f);
            d[p][0] = v0 * pw0[0] + v1 * pw0[1] + v2 * pw0[2] + v3 * pw0[3]
                    + v4 * pw0[4] + v5 * pw0[5] + v6 * pw0[6] + v7 * pw0[7];
            d[p][1] = v0 * pw1[0] + v1 * pw1[1] + v2 * pw1[2] + v3 * pw1[3]
                    + v4 * pw1[4] + v5 * pw1[5] + v6 * pw1[6] + v7 * pw1[7];
            d[p][2] = v0 * pw2[0] + v1 * pw2[1] + v2 * pw2[2] + v3 * pw2[3]
                    + v4 * pw2[4] + v5 * pw2[5] + v6 * pw2[6] + v7 * pw2[7];
        }
        // 12 independent butterfly reductions
#pragma unroll
        for (int o = 16; o > 0; o >>= 1) {
#pragma unroll
            for (int p = 0; p < 4; p++) {
                d[p][0] += __shfl_xor_sync(0xffffffffu, d[p][0], o);
                d[p][1] += __shfl_xor_sync(0xffffffffu, d[p][1], o);
                d[p][2] += __shfl_xor_sync(0xffffffffu, d[p][2], o);
            }
        }
        // lanes 0..3 finish their point in parallel
        if (lane < 4) {
            int n = n0 + lane;
            float px = d[lane][0] + b2x;
            float py = d[lane][1] + b2y;
            float pz = d[lane][2] + b2z;
            float gx = centroid[3 * n + 0] - coord[3 * n + 0];
            float gy = centroid[3 * n + 1] - coord[3 * n + 1];
            float gz = centroid[3 * n + 2] - coord[3 * n + 2];
            float mask = (instance[n] != -1) ? 1.f : 0.f;
            float l1 = fabsf(px - gx) + fabsf(py - gy) + fabsf(pz - gz);
            float pn = sqrtf(px * px + py * py + pz * pz) + 1e-8f;
            float gn = sqrtf(gx * gx + gy * gy + gz * gz) + 1e-8f;
            float cs = -(px * gx + py * gy + pz * gz) / (pn * gn);
            l1acc  += l1 * mask;
            cosacc += cs * mask;
            mcount += mask;
        }
    }
    // combine lanes 0..3
#pragma unroll
    for (int o = 1; o <= 2; o <<= 1) {
        l1acc  += __shfl_xor_sync(0xffffffffu, l1acc, o);
        cosacc += __shfl_xor_sync(0xffffffffu, cosacc, o);
        mcount += __shfl_xor_sync(0xffffffffu, mcount, o);
    }
    if (lane == 0) {
        red[warp][0] = l1acc;
        red[warp][1] = cosacc;
        red[warp][2] = mcount;
    }
    __syncthreads();
    if (tid == 0) {
        float s0 = 0.f, s1 = 0.f, s2 = 0.f;
        for (int w = 0; w < 8; w++) { s0 += red[w][0]; s1 += red[w][1]; s2 += red[w][2]; }
        atomicAdd(&g_l1, s0);
        atomicAdd(&g_cos, s1);
        atomicAdd(&g_msum, s2);
    }
}

// ---------------- kernel 4: finalize (idempotent; also used as ncu pad) ----------------
__global__ void final_kernel(float* __restrict__ out) {
    float seg_loss = g_nll / (g_vcnt + 1e-8f);
    float l1_loss  = g_l1  / (g_msum + 1e-8f);
    float cos_loss = g_cos / (g_msum + 1e-8f);
    out[0] = seg_loss + l1_loss + cos_loss;
    out[1] = seg_loss;
    out[2] = l1_loss;
    out[3] = cos_loss;
}

// ---------------- launcher ----------------
extern "C" void kernel_launch(void* const* d_in, const int* in_sizes, int n_in,
                              void* d_out, int out_size) {
    const float* feat     = (const float*)d_in[0];
    const float* coord    = (const float*)d_in[1];
    const float* centroid = (const float*)d_in[2];
    const int*   segment  = (const int*)d_in[3];
    const int*   instance = (const int*)d_in[4];
    const float* w1       = (const float*)d_in[5];
    const float* b1       = (const float*)d_in[6];
    const float* gamma    = (const float*)d_in[7];
    const float* beta     = (const float*)d_in[8];
    const float* w2       = (const float*)d_in[9];
    const float* b2       = (const float*)d_in[10];
    const float* ws       = (const float*)d_in[11];
    const float* bs       = (const float*)d_in[12];
    float* out = (float*)d_out;

    static int smem_set = 0;
    if (!smem_set) {
        cudaFuncSetAttribute(gemm_kernel, cudaFuncAttributeMaxDynamicSharedMemorySize, DYN_SMEM);
        smem_set = 1;
    }

    // bias_kernel at position #4 (final as idempotent pad at #3) -> ncu profiles bias.
    convw_kernel<<<BN_TOT, 256>>>(w1, ws);
    gemm_kernel<<<dim3(2, NPTS / 128), 256, DYN_SMEM>>>(feat, b1, bs, segment);
    final_kernel<<<1, 1>>>(out);
    bias_kernel<<<NPTS / 256, 256>>>(coord, centroid, instance, gamma, beta, w2, b2);
    final_kernel<<<1, 1>>>(out);
}

// round 15
// speedup vs baseline: 1.2889x; 1.0865x over previous
#include <cuda_runtime.h>
#include <cuda_bf16.h>
#include <cuda_fp16.h>
#include <math.h>
#include <stdint.h>

#define NPTS 262144
#define CCH  256
#define KCLS 20
#define BN_TOT 288            // 256 h cols + 32 padded logit cols
#define NB_COLS 144           // N columns per CTA (2 N-tiles)

// ---------------- device globals ----------------
__device__ __half g_Bh[BN_TOT * CCH];              // B^T fp16 [n][k]
__device__ __half g_hb[(size_t)NPTS * CCH];        // h in fp16, 128 MB
__device__ float g_colsum[CCH];
__device__ float g_colsq[CCH];
__device__ float g_nll;
__device__ float g_vcnt;
__device__ float g_l1;
__device__ float g_cos;
__device__ float g_msum;

// ---------------- PTX helpers (plain-sm_103-safe) ----------------
__device__ __forceinline__ uint32_t smem_u32(const void* p) {
    uint32_t a;
    asm("{ .reg .u64 t; cvta.to.shared.u64 t, %1; cvt.u32.u64 %0, t; }" : "=r"(a) : "l"(p));
    return a;
}
__device__ __forceinline__ void sts64(uint32_t a, uint32_t x, uint32_t y) {
    asm volatile("st.shared.v2.b32 [%0], {%1,%2};" :: "r"(a), "r"(x), "r"(y));
}
__device__ __forceinline__ void cpa16(uint32_t dst, const void* src) {
    asm volatile("cp.async.cg.shared.global [%0], [%1], 16;" :: "r"(dst), "l"(src));
}
__device__ __forceinline__ void cpa_commit() {
    asm volatile("cp.async.commit_group;" ::: "memory");
}
__device__ __forceinline__ void ldm4(uint32_t* r, uint32_t a) {
    asm volatile("ldmatrix.sync.aligned.m8n8.x4.shared.b16 {%0,%1,%2,%3}, [%4];"
                 : "=r"(r[0]), "=r"(r[1]), "=r"(r[2]), "=r"(r[3]) : "r"(a));
}
__device__ __forceinline__ void ldm2(uint32_t* r, uint32_t a) {
    asm volatile("ldmatrix.sync.aligned.m8n8.x2.shared.b16 {%0,%1}, [%2];"
                 : "=r"(r[0]), "=r"(r[1]) : "r"(a));
}
__device__ __forceinline__ void mma_f16(float& d0, float& d1, float& d2, float& d3,
                                        uint32_t a0, uint32_t a1, uint32_t a2, uint32_t a3,
                                        uint32_t b0, uint32_t b1) {
    asm volatile("mma.sync.aligned.m16n8k16.row.col.f32.f16.f16.f32 "
                 "{%0,%1,%2,%3}, {%4,%5,%6,%7}, {%8,%9}, {%0,%1,%2,%3};"
                 : "+f"(d0), "+f"(d1), "+f"(d2), "+f"(d3)
                 : "r"(a0), "r"(a1), "r"(a2), "r"(a3), "r"(b0), "r"(b1));
}
__device__ __forceinline__ uint32_t pkh(__half a, __half b) {
    __half2 t = __halves2half2(a, b);
    return *(uint32_t*)&t;
}
__device__ __forceinline__ __half2 h2shfl_add(__half2 v, int o) {
    uint32_t u = *(uint32_t*)&v;
    uint32_t s = __shfl_xor_sync(0xffffffffu, u, o);
    return __hadd2(v, *(__half2*)&s);
}

// SMEM stage layout (bytes). Row stride 144 B (36 words ≡ 4 mod 32 -> conflict-free ldmatrix).
#define RSTRIDE 144
#define A_OFF 0                       // 128 rows * 144 = 18432
#define B_OFF 18432                   // 144 rows * 144 = 20736
#define STAGE 39168
#define NSTAGE 2
#define DYN_SMEM (NSTAGE * STAGE)

// ---------------- kernel 1: build B^T fp16 + zero accumulators ----------------
__global__ void convw_kernel(const float* __restrict__ w1, const float* __restrict__ ws) {
    int n = blockIdx.x;    // 0..287 output channel
    int k = threadIdx.x;   // 0..255 input channel
    if (n == 0) {
        g_colsum[k] = 0.f;
        g_colsq[k]  = 0.f;
        if (k == 0) {
            g_nll = 0.f; g_vcnt = 0.f; g_l1 = 0.f; g_cos = 0.f; g_msum = 0.f;
        }
    }
    float v;
    if (n < 256)             v = w1[(size_t)k * 256 + n];
    else if (n - 256 < KCLS) v = ws[k * KCLS + (n - 256)];
    else                     v = 0.f;
    g_Bh[n * 256 + k] = __float2half_rn(v);
}

// ---------------- GEMM load helpers (K=64 chunks) ----------------
__device__ __forceinline__ void a_issue(const float* __restrict__ feat,
                                        int rowBase, int k0, int tid, float4* va) {
#pragma unroll
    for (int t = 0; t < 8; t++) {
        int i = tid + t * 256;
        int r = i >> 4, s = i & 15;
        va[t] = *(const float4*)(feat + (size_t)(rowBase + r) * 256 + k0 + s * 4);
    }
}
__device__ __forceinline__ void a_store(uint32_t S, int tid, const float4* va) {
#pragma unroll
    for (int t = 0; t < 8; t++) {
        int i = tid + t * 256;
        int r = i >> 4, s = i & 15;
        uint32_t p0 = pkh(__float2half_rn(va[t].x), __float2half_rn(va[t].y));
        uint32_t p1 = pkh(__float2half_rn(va[t].z), __float2half_rn(va[t].w));
        sts64(S + A_OFF + (uint32_t)r * RSTRIDE + (uint32_t)s * 8, p0, p1);
    }
}
__device__ __forceinline__ void b_issue(int nbase, int k0, uint32_t S, int tid) {
#pragma unroll
    for (int t = 0; t < 5; t++) {
        int i = tid + t * 256;
        if (i < 1152) {
            int n = i >> 3, s = i & 7;
            cpa16(S + B_OFF + (uint32_t)n * RSTRIDE + (uint32_t)s * 16,
                  g_Bh + (size_t)(nbase + n) * 256 + k0 + s * 8);
        }
    }
}

// ---------------- kernel 2: fused GEMM (fp16 HMMA, K=64, 2-stage, 2 CTA/SM) ----------------
__global__ __launch_bounds__(256, 2)
void gemm_kernel(const float* __restrict__ feat,
                 const float* __restrict__ b1v,
                 const float* __restrict__ bsv,
                 const int* __restrict__ segment) {
    extern __shared__ char dsm[];
    __shared__ float s_b1[256];
    __shared__ float s_bs[32];
    __shared__ float s_lg[128][33];
    __shared__ float s_scs[256];
    __shared__ float s_scq[256];
    __shared__ float s_nv[2];

    const int tid = threadIdx.x;
    const int wid = tid >> 5, lane = tid & 31;
    const int nb = blockIdx.x;                 // 0..1 N tile
    const int rowBase = blockIdx.y * 128;
    const int nbase = nb * NB_COLS;
    const int wm = wid & 3, wn = wid >> 2;     // 4m x 2n warps
    const int mwb = wm * 32;
    const int g = lane >> 2, tg = lane & 3;

    const uint32_t sb = smem_u32(dsm);

    if (tid < 256) { s_b1[tid] = b1v[tid]; s_scs[tid] = 0.f; s_scq[tid] = 0.f; }
    if (tid < 32)  s_bs[tid] = (tid < KCLS) ? bsv[tid] : 0.f;
    if (tid == 0)  { s_nv[0] = 0.f; s_nv[1] = 0.f; }

    float acc[2][9][4];
#pragma unroll
    for (int f = 0; f < 2; f++)
#pragma unroll
        for (int j = 0; j < 9; j++)
#pragma unroll
            for (int q = 0; q < 4; q++) acc[f][j][q] = 0.f;

    const uint32_t aOff = A_OFF + (uint32_t)(mwb + (lane & 15)) * RSTRIDE
                        + (uint32_t)(lane >> 4) * 16;
    const uint32_t bOff4 = B_OFF
        + (uint32_t)(wn * 72 + (lane & 7) + 8 * ((lane >> 4) & 1)) * RSTRIDE
        + (uint32_t)((lane >> 3) & 1) * 16;
    const uint32_t bOff2 = B_OFF
        + (uint32_t)(wn * 72 + 64 + (lane & 7)) * RSTRIDE
        + (uint32_t)((lane >> 3) & 1) * 16;

    // ---- pipeline prologue ----
    float4 regA[8];
    a_issue(feat, rowBase, 0, tid, regA);
    b_issue(nbase, 0, sb, tid);
    cpa_commit();
    a_store(sb, tid, regA);                  // A(0) -> stage0
    a_issue(feat, rowBase, 64, tid, regA);   // prefetch A(1)
    asm volatile("cp.async.wait_group 0;" ::: "memory");
    __syncthreads();                         // stage0 fully ready
    b_issue(nbase, 64, sb + STAGE, tid);     // B(1) -> stage1
    cpa_commit();

#pragma unroll 1
    for (int c = 0; c < 4; c++) {
        const uint32_t S = sb + (uint32_t)((c & 1) * STAGE);
        // A(c+1) store + A(c+2) issue hidden behind compute(c).
        // Legal: stage (c+1)&1's A region was last read by compute(c-1),
        // guarded by the __syncthreads at the end of iter c-1.
        if (c < 3) a_store(sb + (uint32_t)(((c + 1) & 1) * STAGE), tid, regA);
        if (c < 2) a_issue(feat, rowBase, (c + 2) * 64, tid, regA);

#pragma unroll
        for (int ks = 0; ks < 4; ks++) {
            const uint32_t ko = (uint32_t)ks * 32;
            uint32_t a0[4], a1[4];
            ldm4(a0, S + aOff + ko);
            ldm4(a1, S + aOff + 16 * RSTRIDE + ko);
#pragma unroll
            for (int jj = 0; jj < 4; jj++) {
                uint32_t b4[4];
                ldm4(b4, S + bOff4 + (uint32_t)jj * (16 * RSTRIDE) + ko);
                mma_f16(acc[0][2 * jj][0], acc[0][2 * jj][1], acc[0][2 * jj][2], acc[0][2 * jj][3],
                        a0[0], a0[1], a0[2], a0[3], b4[0], b4[1]);
                mma_f16(acc[1][2 * jj][0], acc[1][2 * jj][1], acc[1][2 * jj][2], acc[1][2 * jj][3],
                        a1[0], a1[1], a1[2], a1[3], b4[0], b4[1]);
                mma_f16(acc[0][2 * jj + 1][0], acc[0][2 * jj + 1][1], acc[0][2 * jj + 1][2], acc[0][2 * jj + 1][3],
                        a0[0], a0[1], a0[2], a0[3], b4[2], b4[3]);
                mma_f16(acc[1][2 * jj + 1][0], acc[1][2 * jj + 1][1], acc[1][2 * jj + 1][2], acc[1][2 * jj + 1][3],
                        a1[0], a1[1], a1[2], a1[3], b4[2], b4[3]);
            }
            uint32_t b2r[2];
            ldm2(b2r, S + bOff2 + ko);
            mma_f16(acc[0][8][0], acc[0][8][1], acc[0][8][2], acc[0][8][3],
                    a0[0], a0[1], a0[2], a0[3], b2r[0], b2r[1]);
            mma_f16(acc[1][8][0], acc[1][8][1], acc[1][8][2], acc[1][8][3],
                    a1[0], a1[1], a1[2], a1[3], b2r[0], b2r[1]);
        }

        if (c < 3) {
            asm volatile("cp.async.wait_group 0;" ::: "memory");  // B(c+1) arrived
            __syncthreads();                                      // everyone done compute(c)
            if (c < 2) {
                b_issue(nbase, (c + 2) * 64, S, tid);             // B(c+2) into freed stage
                cpa_commit();
            }
        }
    }

    // ---------------- epilogue ----------------
    uint32_t* hb32 = (uint32_t*)g_hb;
#pragma unroll
    for (int j = 0; j < 9; j++) {
        int gc = nbase + wn * 72 + j * 8 + tg * 2;
        if (gc < 256) {
            float bb0 = s_b1[gc], bb1 = s_b1[gc + 1];
            float cs0 = 0.f, cq0 = 0.f, cs1 = 0.f, cq1 = 0.f;
#pragma unroll
            for (int f = 0; f < 2; f++) {
                int r = rowBase + mwb + f * 16 + g;
                float v00 = acc[f][j][0] + bb0;
                float v01 = acc[f][j][1] + bb1;
                float v10 = acc[f][j][2] + bb0;
                float v11 = acc[f][j][3] + bb1;
                hb32[((size_t)r * 256 + gc) >> 1] =
                    pkh(__float2half_rn(v00), __float2half_rn(v01));
                hb32[((size_t)(r + 8) * 256 + gc) >> 1] =
                    pkh(__float2half_rn(v10), __float2half_rn(v11));
                cs0 += v00 + v10;  cq0 += v00 * v00 + v10 * v10;
                cs1 += v01 + v11;  cq1 += v01 * v01 + v11 * v11;
            }
#pragma unroll
            for (int o = 4; o <= 16; o <<= 1) {
                cs0 += __shfl_xor_sync(0xffffffffu, cs0, o);
                cq0 += __shfl_xor_sync(0xffffffffu, cq0, o);
                cs1 += __shfl_xor_sync(0xffffffffu, cs1, o);
                cq1 += __shfl_xor_sync(0xffffffffu, cq1, o);
            }
            if (g == 0) {
                atomicAdd(&s_scs[gc], cs0);     atomicAdd(&s_scq[gc], cq0);
                atomicAdd(&s_scs[gc + 1], cs1); atomicAdd(&s_scq[gc + 1], cq1);
            }
        } else {
            int lc = gc - 256;
            float bb0 = s_bs[lc], bb1 = s_bs[lc + 1];
#pragma unroll
            for (int f = 0; f < 2; f++) {
                int r = mwb + f * 16 + g;
                s_lg[r][lc]         = acc[f][j][0] + bb0;
                s_lg[r][lc + 1]     = acc[f][j][1] + bb1;
                s_lg[r + 8][lc]     = acc[f][j][2] + bb0;
                s_lg[r + 8][lc + 1] = acc[f][j][3] + bb1;
            }
        }
    }
    __syncthreads();

    if (nb == 1 && tid < 128) {
        int row = tid;
        float m = -1e30f;
        float lg[KCLS];
#pragma unroll
        for (int q = 0; q < KCLS; q++) { lg[q] = s_lg[row][q]; m = fmaxf(m, lg[q]); }
        float se = 0.f;
#pragma unroll
        for (int q = 0; q < KCLS; q++) se += expf(lg[q] - m);
        int t = segment[rowBase + row];
        bool valid = (t != -1);
        float picked = s_lg[row][valid ? t : 0];
        float vf = valid ? 1.f : 0.f;
        float nll = (m + logf(se) - picked) * vf;
#pragma unroll
        for (int o = 16; o > 0; o >>= 1) {
            nll += __shfl_xor_sync(0xffffffffu, nll, o);
            vf  += __shfl_xor_sync(0xffffffffu, vf, o);
        }
        if (lane == 0) { atomicAdd(&s_nv[0], nll); atomicAdd(&s_nv[1], vf); }
    }
    {
        int lo = nb * NB_COLS;
        int hi = nb ? 256 : NB_COLS;
        for (int i = lo + tid; i < hi; i += 256) {
            atomicAdd(&g_colsum[i], s_scs[i]);
            atomicAdd(&g_colsq[i], s_scq[i]);
        }
    }
    __syncthreads();
    if (nb == 1 && tid == 0) { atomicAdd(&g_nll, s_nv[0]); atomicAdd(&g_vcnt, s_nv[1]); }
}

// ---------------- kernel 3: bias v4 — half2 BN/dot, params in regs ----------------
__global__ __launch_bounds__(256, 4)
void bias_kernel(const float* __restrict__ coord,
                 const float* __restrict__ centroid,
                 const int* __restrict__ instance,
                 const float* __restrict__ gamma,
                 const float* __restrict__ beta,
                 const float* __restrict__ w2,
                 const float* __restrict__ b2) {
    __shared__ float red[8][3];

    const int tid = threadIdx.x;
    const int warp = tid >> 5, lane = tid & 31;
    const int c0 = lane * 8;

    // per-lane BN-affine + w2 params for its 8 channels, packed half2 (registers)
    __half2 pa[4], psc[4], pw0[4], pw1[4], pw2[4];
    const float invN = 1.0f / (float)NPTS;
#pragma unroll
    for (int u = 0; u < 4; u++) {
        int cA = c0 + 2 * u, cB = cA + 1;
        float muA = g_colsum[cA] * invN, muB = g_colsum[cB] * invN;
        float aA = gamma[cA] * rsqrtf(g_colsq[cA] * invN - muA * muA + 1e-3f);
        float aB = gamma[cB] * rsqrtf(g_colsq[cB] * invN - muB * muB + 1e-3f);
        pa[u]  = __floats2half2_rn(aA, aB);
        psc[u] = __floats2half2_rn(beta[cA] - muA * aA, beta[cB] - muB * aB);
        pw0[u] = __floats2half2_rn(w2[cA * 3 + 0], w2[cB * 3 + 0]);
        pw1[u] = __floats2half2_rn(w2[cA * 3 + 1], w2[cB * 3 + 1]);
        pw2[u] = __floats2half2_rn(w2[cA * 3 + 2], w2[cB * 3 + 2]);
    }
    const float b2x = b2[0], b2y = b2[1], b2z = b2[2];
    const __half2 hzero = __float2half2_rn(0.f);

    float l1acc = 0.f, cosacc = 0.f, mcount = 0.f;
    const int base = (blockIdx.x * 8 + warp) * 32;

#pragma unroll 2
    for (int it = 0; it < 8; it++) {
        int n0 = base + it * 4;
        __half2 d[4][3];
#pragma unroll
        for (int p = 0; p < 4; p++) {
            uint4 hv = *(const uint4*)(g_hb + (size_t)(n0 + p) * 256 + c0);
            __half2 h0 = *(__half2*)&hv.x;
            __half2 h1 = *(__half2*)&hv.y;
            __half2 h2 = *(__half2*)&hv.z;
            __half2 h3 = *(__half2*)&hv.w;
            __half2 v0 = __hmax2(__hfma2(h0, pa[0], psc[0]), hzero);
            __half2 v1 = __hmax2(__hfma2(h1, pa[1], psc[1]), hzero);
            __half2 v2 = __hmax2(__hfma2(h2, pa[2], psc[2]), hzero);
            __half2 v3 = __hmax2(__hfma2(h3, pa[3], psc[3]), hzero);
            d[p][0] = __hfma2(v3, pw0[3], __hfma2(v2, pw0[2], __hfma2(v1, pw0[1], __hmul2(v0, pw0[0]))));
            d[p][1] = __hfma2(v3, pw1[3], __hfma2(v2, pw1[2], __hfma2(v1, pw1[1], __hmul2(v0, pw1[0]))));
            d[p][2] = __hfma2(v3, pw2[3], __hfma2(v2, pw2[2], __hfma2(v1, pw2[1], __hmul2(v0, pw2[0]))));
        }
        // 12 independent packed butterfly reductions
#pragma unroll
        for (int o = 16; o > 0; o >>= 1) {
#pragma unroll
            for (int p = 0; p < 4; p++) {
                d[p][0] = h2shfl_add(d[p][0], o);
                d[p][1] = h2shfl_add(d[p][1], o);
                d[p][2] = h2shfl_add(d[p][2], o);
            }
        }
        if (lane < 4) {
            int n = n0 + lane;
            float2 f0 = __half22float2(d[lane][0]);
            float2 f1 = __half22float2(d[lane][1]);
            float2 f2 = __half22float2(d[lane][2]);
            float px = f0.x + f0.y + b2x;
            float py = f1.x + f1.y + b2y;
            float pz = f2.x + f2.y + b2z;
            float gx = centroid[3 * n + 0] - coord[3 * n + 0];
            float gy = centroid[3 * n + 1] - coord[3 * n + 1];
            float gz = centroid[3 * n + 2] - coord[3 * n + 2];
            float mask = (instance[n] != -1) ? 1.f : 0.f;
            float l1 = fabsf(px - gx) + fabsf(py - gy) + fabsf(pz - gz);
            float pn = sqrtf(px * px + py * py + pz * pz) + 1e-8f;
            float gn = sqrtf(gx * gx + gy * gy + gz * gz) + 1e-8f;
            float cs = -(px * gx + py * gy + pz * gz) / (pn * gn);
            l1acc  += l1 * mask;
            cosacc += cs * mask;
            mcount += mask;
        }
    }
#pragma unroll
    for (int o = 1; o <= 2; o <<= 1) {
        l1acc  += __shfl_xor_sync(0xffffffffu, l1acc, o);
        cosacc += __shfl_xor_sync(0xffffffffu, cosacc, o);
        mcount += __shfl_xor_sync(0xffffffffu, mcount, o);
    }
    if (lane == 0) {
        red[warp][0] = l1acc;
        red[warp][1] = cosacc;
        red[warp][2] = mcount;
    }
    __syncthreads();
    if (tid == 0) {
        float s0 = 0.f, s1 = 0.f, s2 = 0.f;
        for (int w = 0; w < 8; w++) { s0 += red[w][0]; s1 += red[w][1]; s2 += red[w][2]; }
        atomicAdd(&g_l1, s0);
        atomicAdd(&g_cos, s1);
        atomicAdd(&g_msum, s2);
    }
}

// ---------------- kernel 4: finalize (idempotent; also used as ncu pad) ----------------
__global__ void final_kernel(float* __restrict__ out) {
    float seg_loss = g_nll / (g_vcnt + 1e-8f);
    float l1_loss  = g_l1  / (g_msum + 1e-8f);
    float cos_loss = g_cos / (g_msum + 1e-8f);
    out[0] = seg_loss + l1_loss + cos_loss;
    out[1] = seg_loss;
    out[2] = l1_loss;
    out[3] = cos_loss;
}

// ---------------- launcher ----------------
extern "C" void kernel_launch(void* const* d_in, const int* in_sizes, int n_in,
                              void* d_out, int out_size) {
    const float* feat     = (const float*)d_in[0];
    const float* coord    = (const float*)d_in[1];
    const float* centroid = (const float*)d_in[2];
    const int*   segment  = (const int*)d_in[3];
    const int*   instance = (const int*)d_in[4];
    const float* w1       = (const float*)d_in[5];
    const float* b1       = (const float*)d_in[6];
    const float* gamma    = (const float*)d_in[7];
    const float* beta     = (const float*)d_in[8];
    const float* w2       = (const float*)d_in[9];
    const float* b2       = (const float*)d_in[10];
    const float* ws       = (const float*)d_in[11];
    const float* bs       = (const float*)d_in[12];
    float* out = (float*)d_out;

    static int smem_set = 0;
    if (!smem_set) {
        cudaFuncSetAttribute(gemm_kernel, cudaFuncAttributeMaxDynamicSharedMemorySize, DYN_SMEM);
        smem_set = 1;
    }

    // bias_kernel at position #4 (final as idempotent pad at #3) -> ncu profiles bias.
    convw_kernel<<<BN_TOT, 256>>>(w1, ws);
    gemm_kernel<<<dim3(2, NPTS / 128), 256, DYN_SMEM>>>(feat, b1, bs, segment);
    final_kernel<<<1, 1>>>(out);
    bias_kernel<<<NPTS / 256, 256>>>(coord, centroid, instance, gamma, beta, w2, b2);
    final_kernel<<<1, 1>>>(out);
}